// round 4
// baseline (speedup 1.0000x reference)
#include <cuda_runtime.h>
#include <math.h>

#define B_  32
#define S_  50
#define Q_  75
#define T_  128
#define F_  64
#define D_  256
#define KW  5
#define NS  (B_*S_)        // 1600 support samples
#define NQ  (B_*Q_)        // 2400 query samples
#define NTOT (NS+NQ)       // 4000

// Scratch (device globals: allocation-free per harness rules)
__device__ float g_pooled[NTOT * F_];        // 1 MB
__device__ float g_z[NTOT * D_];             // 4 MB
__device__ float g_proto[B_ * KW * D_];      // 160 KB

// ---------------------------------------------------------------------------
// K1: mean-pool over time. One block per sample. 256 threads:
//   f4 = tid & 15 (16 float4 per 64-float feature row), tg = tid >> 4 (16 t-groups)
// Each thread sums 8 time rows (float4), then shared tree-reduce over tg.
// ---------------------------------------------------------------------------
__global__ void __launch_bounds__(256) pool_kernel(const float* __restrict__ sx,
                                                   const float* __restrict__ qx) {
    int sn = blockIdx.x;
    const float4* src;
    if (sn < NS) src = reinterpret_cast<const float4*>(sx) + (size_t)sn * (T_ * F_ / 4);
    else         src = reinterpret_cast<const float4*>(qx) + (size_t)(sn - NS) * (T_ * F_ / 4);

    int tid = threadIdx.x;
    int f4  = tid & 15;
    int tg  = tid >> 4;

    float4 acc = make_float4(0.f, 0.f, 0.f, 0.f);
    #pragma unroll
    for (int i = 0; i < 8; i++) {
        int t = tg + i * 16;
        float4 v = src[t * 16 + f4];
        acc.x += v.x; acc.y += v.y; acc.z += v.z; acc.w += v.w;
    }

    __shared__ float4 sm[256];
    sm[tid] = acc;
    __syncthreads();
    // reduce over tg (stride 16 in tid-space)
    #pragma unroll
    for (int s = 128; s >= 16; s >>= 1) {
        if (tid < s) {
            float4 o = sm[tid + s];
            float4 m = sm[tid];
            m.x += o.x; m.y += o.y; m.z += o.z; m.w += o.w;
            sm[tid] = m;
        }
        __syncthreads();
    }
    if (tid < 16) {
        float4 m = sm[tid];
        const float inv = 1.0f / (float)T_;
        m.x *= inv; m.y *= inv; m.z *= inv; m.w *= inv;
        reinterpret_cast<float4*>(g_pooled)[sn * 16 + tid] = m;
    }
}

// ---------------------------------------------------------------------------
// K2: projection z = pooled @ W + b. Tile of 16 samples per block.
// thread = output dim d (256 threads). W row W[f*256+d] loaded once per f,
// reused for 16 samples (amortizes W L2 traffic 16x).
// ---------------------------------------------------------------------------
#define TILE_N 16
__global__ void __launch_bounds__(256) proj_kernel(const float* __restrict__ Wm,
                                                   const float* __restrict__ bv) {
    int tile = blockIdx.x;          // NTOT/TILE_N = 250
    int d    = threadIdx.x;

    __shared__ float sp[TILE_N * F_];   // 4 KB
    for (int i = threadIdx.x; i < TILE_N * F_; i += 256)
        sp[i] = g_pooled[tile * TILE_N * F_ + i];
    __syncthreads();

    float acc[TILE_N];
    #pragma unroll
    for (int s = 0; s < TILE_N; s++) acc[s] = 0.f;

    #pragma unroll 4
    for (int f = 0; f < F_; f++) {
        float w = Wm[f * D_ + d];
        #pragma unroll
        for (int s = 0; s < TILE_N; s++)
            acc[s] += sp[s * F_ + f] * w;   // shared broadcast (same addr per warp)
    }

    float bb = bv[d];
    #pragma unroll
    for (int s = 0; s < TILE_N; s++)
        g_z[(size_t)(tile * TILE_N + s) * D_ + d] = acc[s] + bb;
}

// ---------------------------------------------------------------------------
// K3: prototypes = label-grouped mean of support_z. One block per (b,k).
// ---------------------------------------------------------------------------
__global__ void __launch_bounds__(256) proto_kernel(const int* __restrict__ y) {
    int bk = blockIdx.x;            // B_*KW = 160
    int b  = bk / KW;
    int k  = bk % KW;
    int d  = threadIdx.x;

    __shared__ int ys[S_];
    if (threadIdx.x < S_) ys[threadIdx.x] = y[b * S_ + threadIdx.x];
    __syncthreads();

    float sum = 0.f;
    int cnt = 0;
    #pragma unroll 10
    for (int s = 0; s < S_; s++) {
        if (ys[s] == k) {
            sum += g_z[(size_t)(b * S_ + s) * D_ + d];
            cnt++;
        }
    }
    g_proto[bk * D_ + d] = (cnt > 0) ? (sum / (float)cnt) : 0.f;
}

// ---------------------------------------------------------------------------
// K4: logits = -||query_z - proto||_2. One block per (b,q); protos in shared;
// warp-shuffle reduction over D=256.
// ---------------------------------------------------------------------------
__global__ void __launch_bounds__(256) dist_kernel(float* __restrict__ out) {
    int bq = blockIdx.x;            // NQ = 2400; bq = b*Q_ + q
    int b  = bq / Q_;
    int tid = threadIdx.x;

    __shared__ float psh[KW * D_];  // 5 KB
    for (int i = tid; i < KW * D_; i += 256)
        psh[i] = g_proto[b * KW * D_ + i];

    float qv = g_z[(size_t)(NS + bq) * D_ + tid];
    __syncthreads();

    __shared__ float warpsum[8];
    for (int k = 0; k < KW; k++) {
        float diff = qv - psh[k * D_ + tid];
        float v = diff * diff;
        #pragma unroll
        for (int off = 16; off > 0; off >>= 1)
            v += __shfl_xor_sync(0xffffffffu, v, off);
        if ((tid & 31) == 0) warpsum[tid >> 5] = v;
        __syncthreads();
        if (tid < 8) {
            float w = warpsum[tid];
            #pragma unroll
            for (int off = 4; off > 0; off >>= 1)
                w += __shfl_xor_sync(0xffu, w, off);
            if (tid == 0) out[bq * KW + k] = -sqrtf(w);
        }
        __syncthreads();
    }
}

// ---------------------------------------------------------------------------
// Inputs (metadata order): support_x f32, support_y i32, query_x f32, W f32, b f32
// Output: f32 [B*Q, KW] = [2400, 5]
// ---------------------------------------------------------------------------
extern "C" void kernel_launch(void* const* d_in, const int* in_sizes, int n_in,
                              void* d_out, int out_size) {
    const float* sx = (const float*)d_in[0];
    const int*   sy = (const int*)  d_in[1];
    const float* qx = (const float*)d_in[2];
    const float* Wm = (const float*)d_in[3];
    const float* bv = (const float*)d_in[4];
    float* out = (float*)d_out;

    pool_kernel <<<NTOT,          256>>>(sx, qx);
    proj_kernel <<<NTOT / TILE_N, 256>>>(Wm, bv);
    proto_kernel<<<B_ * KW,       256>>>(sy);
    dist_kernel <<<NQ,            256>>>(out);
}

// round 5
// speedup vs baseline: 1.0747x; 1.0747x over previous
#include <cuda_runtime.h>
#include <math.h>

#define B_  32
#define S_  50
#define Q_  75
#define T_  128
#define F_  64
#define D_  256
#define KW  5
#define NS  (B_*S_)          // 1600 support samples
#define NQ  (B_*Q_)          // 2400 query samples
#define NPROJ (NQ + B_*KW)   // 2560 vectors to project: queries then prototypes

// Scratch (device globals: allocation-free per harness rules)
__device__ float g_spooled[NS * F_];      // pooled support features  (400 KB)
__device__ float g_feat[NPROJ * F_];      // [queries | proto_pooled] (640 KB)
__device__ float g_zall[NPROJ * D_];      // projected               (2.5 MB)

// ---------------------------------------------------------------------------
// K1: mean-pool over time. One block per sample. 256 threads:
//   f4 = tid & 15 (16 float4 per 64-float row), tg = tid >> 4 (16 t-groups)
// 8 independent float4 loads per thread (MLP=8), shared tree-reduce.
// Support -> g_spooled; queries -> g_feat[0..NQ).
// ---------------------------------------------------------------------------
__global__ void __launch_bounds__(256) pool_kernel(const float* __restrict__ sx,
                                                   const float* __restrict__ qx) {
    int sn = blockIdx.x;
    const float4* src;
    float4* dst;
    if (sn < NS) {
        src = reinterpret_cast<const float4*>(sx) + (size_t)sn * (T_ * F_ / 4);
        dst = reinterpret_cast<float4*>(g_spooled) + sn * 16;
    } else {
        src = reinterpret_cast<const float4*>(qx) + (size_t)(sn - NS) * (T_ * F_ / 4);
        dst = reinterpret_cast<float4*>(g_feat) + (sn - NS) * 16;
    }

    int tid = threadIdx.x;
    int f4  = tid & 15;
    int tg  = tid >> 4;

    float4 acc = make_float4(0.f, 0.f, 0.f, 0.f);
    #pragma unroll
    for (int i = 0; i < 8; i++) {
        float4 v = src[(tg + i * 16) * 16 + f4];
        acc.x += v.x; acc.y += v.y; acc.z += v.z; acc.w += v.w;
    }

    __shared__ float4 sm[256];
    sm[tid] = acc;
    __syncthreads();
    #pragma unroll
    for (int s = 128; s >= 16; s >>= 1) {
        if (tid < s) {
            float4 o = sm[tid + s];
            float4 m = sm[tid];
            m.x += o.x; m.y += o.y; m.z += o.z; m.w += o.w;
            sm[tid] = m;
        }
        __syncthreads();
    }
    if (tid < 16) {
        float4 m = sm[tid];
        const float inv = 1.0f / (float)T_;
        m.x *= inv; m.y *= inv; m.z *= inv; m.w *= inv;
        dst[tid] = m;
    }
}

// ---------------------------------------------------------------------------
// K2: 64-dim prototypes (projection is linear; class-mean commutes with it).
// One block per episode b; 64 threads (thread = feature f).
// 5 predicated accumulators avoid label-indexed register arrays.
// Writes g_feat[NQ + b*KW + k].
// ---------------------------------------------------------------------------
__global__ void __launch_bounds__(64) proto_kernel(const int* __restrict__ y) {
    int b = blockIdx.x;
    int f = threadIdx.x;

    __shared__ int ys[S_];
    if (f < S_) ys[f] = y[b * S_ + f];
    // second chunk of labels (S_=50 < 64, single pass covers it)
    __syncthreads();

    float acc0 = 0.f, acc1 = 0.f, acc2 = 0.f, acc3 = 0.f, acc4 = 0.f;
    int   c0 = 0,   c1 = 0,   c2 = 0,   c3 = 0,   c4 = 0;
    #pragma unroll 10
    for (int s = 0; s < S_; s++) {
        float v = g_spooled[(b * S_ + s) * F_ + f];
        int l = ys[s];
        if (l == 0) { acc0 += v; c0++; }
        if (l == 1) { acc1 += v; c1++; }
        if (l == 2) { acc2 += v; c2++; }
        if (l == 3) { acc3 += v; c3++; }
        if (l == 4) { acc4 += v; c4++; }
    }
    float* dst = g_feat + (NQ + b * KW) * F_ + f;
    dst[0 * F_] = c0 ? acc0 / (float)c0 : 0.f;
    dst[1 * F_] = c1 ? acc1 / (float)c1 : 0.f;
    dst[2 * F_] = c2 ? acc2 / (float)c2 : 0.f;
    dst[3 * F_] = c3 ? acc3 / (float)c3 : 0.f;
    dst[4 * F_] = c4 ? acc4 / (float)c4 : 0.f;
}

// ---------------------------------------------------------------------------
// K3: projection z = feat @ W (bias cancels in the distance -> skipped).
// Tile of 16 vectors per block; thread = output dim d; W row reused 16x.
// NPROJ/16 = 160 blocks.
// ---------------------------------------------------------------------------
#define TILE_N 16
__global__ void __launch_bounds__(256) proj_kernel(const float* __restrict__ Wm) {
    int tile = blockIdx.x;
    int d    = threadIdx.x;

    __shared__ float sp[TILE_N * F_];   // 4 KB
    for (int i = threadIdx.x; i < TILE_N * F_; i += 256)
        sp[i] = g_feat[tile * TILE_N * F_ + i];
    __syncthreads();

    float acc[TILE_N];
    #pragma unroll
    for (int s = 0; s < TILE_N; s++) acc[s] = 0.f;

    #pragma unroll 4
    for (int f = 0; f < F_; f++) {
        float w = Wm[f * D_ + d];
        #pragma unroll
        for (int s = 0; s < TILE_N; s++)
            acc[s] += sp[s * F_ + f] * w;
    }

    #pragma unroll
    for (int s = 0; s < TILE_N; s++)
        g_zall[(size_t)(tile * TILE_N + s) * D_ + d] = acc[s];
}

// ---------------------------------------------------------------------------
// K4: logits = -||qz - proto||.  Warp-per-query, barrier-free inner loop.
// Block = 8 warps = 8 queries of one episode; 10 blocks per episode (80>=75).
// Each lane holds 8 query floats via 2x LDG.128; protos staged in shared.
// ---------------------------------------------------------------------------
__global__ void __launch_bounds__(256) dist_kernel(float* __restrict__ out) {
    int b    = blockIdx.x / 10;
    int blk  = blockIdx.x % 10;
    int warp = threadIdx.x >> 5;
    int lane = threadIdx.x & 31;

    __shared__ float4 psh[KW * (D_ / 4)];   // 5 KB
    {
        const float4* psrc = reinterpret_cast<const float4*>(
            g_zall + (size_t)(NQ + b * KW) * D_);
        for (int i = threadIdx.x; i < KW * (D_ / 4); i += 256)
            psh[i] = psrc[i];
    }
    __syncthreads();

    int q = blk * 8 + warp;
    if (q >= Q_) return;
    int bq = b * Q_ + q;

    const float4* qz = reinterpret_cast<const float4*>(g_zall + (size_t)bq * D_);
    float4 qv0 = qz[lane];
    float4 qv1 = qz[32 + lane];

    #pragma unroll
    for (int k = 0; k < KW; k++) {
        float4 p0 = psh[k * 64 + lane];
        float4 p1 = psh[k * 64 + 32 + lane];
        float d0 = qv0.x - p0.x, d1 = qv0.y - p0.y, d2 = qv0.z - p0.z, d3 = qv0.w - p0.w;
        float d4 = qv1.x - p1.x, d5 = qv1.y - p1.y, d6 = qv1.z - p1.z, d7 = qv1.w - p1.w;
        float v = d0*d0 + d1*d1 + d2*d2 + d3*d3 + d4*d4 + d5*d5 + d6*d6 + d7*d7;
        #pragma unroll
        for (int off = 16; off > 0; off >>= 1)
            v += __shfl_xor_sync(0xffffffffu, v, off);
        if (lane == 0) out[bq * KW + k] = -sqrtf(v);
    }
}

// ---------------------------------------------------------------------------
// Inputs (metadata order): support_x f32, support_y i32, query_x f32, W f32, b f32
// Output: f32 [B*Q, KW] = [2400, 5]
// ---------------------------------------------------------------------------
extern "C" void kernel_launch(void* const* d_in, const int* in_sizes, int n_in,
                              void* d_out, int out_size) {
    const float* sx = (const float*)d_in[0];
    const int*   sy = (const int*)  d_in[1];
    const float* qx = (const float*)d_in[2];
    const float* Wm = (const float*)d_in[3];
    float* out = (float*)d_out;

    pool_kernel <<<NS + NQ,         256>>>(sx, qx);
    proto_kernel<<<B_,              64>>>(sy);
    proj_kernel <<<NPROJ / TILE_N,  256>>>(Wm);
    dist_kernel <<<B_ * 10,         256>>>(out);
}